// round 3
// baseline (speedup 1.0000x reference)
#include <cuda_runtime.h>

// local_field scratch: N = 100000 nodes; round up for safety.
#define MAX_NODES (1 << 17)
__device__ float g_lf[MAX_NODES];
__device__ int g_is32;   // 1 if edge_index is int32, 0 if int64

// Detect index width: interpret first `sample` values as int64; any value
// outside [0, n) means the underlying data is int32 (little-endian pairs
// fuse into huge numbers). Deterministic for fixed input.
__global__ void detect_kernel(const void* ei, int n, int sample) {
    if (threadIdx.x == 0 && blockIdx.x == 0) {
        const long long* p = (const long long*)ei;
        int is32 = 0;
        for (int i = 0; i < sample; i++) {
            long long v = p[i];
            if (v < 0 || v >= (long long)n) { is32 = 1; break; }
        }
        g_is32 = is32;
    }
}

__global__ void zero_lf_kernel(int n) {
    int i = blockIdx.x * blockDim.x + threadIdx.x;
    if (i < n) g_lf[i] = 0.0f;
}

// Each thread handles 4 edges. Uniform branch on index width.
__global__ void edge_kernel(const float* __restrict__ x,
                            const void* __restrict__ ei,
                            long long E) {
    long long t = (long long)blockIdx.x * blockDim.x + threadIdx.x;
    long long nvec = E >> 2;
    int is32 = g_is32;  // uniform load, same for all threads

    int r[4], c[4];
    if (t < nvec) {
        long long base = t << 2;
        if (is32) {
            const int* rows = (const int*)ei;
            const int* cols = rows + E;
            int4 ra = *reinterpret_cast<const int4*>(rows + base);
            int4 ca = *reinterpret_cast<const int4*>(cols + base);
            r[0] = ra.x; r[1] = ra.y; r[2] = ra.z; r[3] = ra.w;
            c[0] = ca.x; c[1] = ca.y; c[2] = ca.z; c[3] = ca.w;
        } else {
            const long long* rows = (const long long*)ei;
            const long long* cols = rows + E;
            longlong2 ra = *reinterpret_cast<const longlong2*>(rows + base);
            longlong2 rb = *reinterpret_cast<const longlong2*>(rows + base + 2);
            longlong2 ca = *reinterpret_cast<const longlong2*>(cols + base);
            longlong2 cb = *reinterpret_cast<const longlong2*>(cols + base + 2);
            r[0] = (int)ra.x; r[1] = (int)ra.y; r[2] = (int)rb.x; r[3] = (int)rb.y;
            c[0] = (int)ca.x; c[1] = (int)ca.y; c[2] = (int)cb.x; c[3] = (int)cb.y;
        }
        float xr[4], xc[4];
#pragma unroll
        for (int k = 0; k < 4; k++) {
            xr[k] = __ldg(x + r[k]);
            xc[k] = __ldg(x + c[k]);
        }
#pragma unroll
        for (int k = 0; k < 4; k++) {
            atomicAdd(&g_lf[r[k]], xr[k] * xc[k]);
        }
    } else if (t == nvec) {
        // tail (E not divisible by 4)
        for (long long e = nvec << 2; e < E; e++) {
            int rr, cc;
            if (is32) {
                const int* rows = (const int*)ei;
                rr = rows[e]; cc = rows[E + e];
            } else {
                const long long* rows = (const long long*)ei;
                rr = (int)rows[e]; cc = (int)rows[E + e];
            }
            atomicAdd(&g_lf[rr], __ldg(x + rr) * __ldg(x + cc));
        }
    }
}

// One thread per node. Weights staged in shared memory (broadcast reads).
__global__ void mlp_kernel(const float* __restrict__ x,
                           const float* __restrict__ w1,
                           const float* __restrict__ b1,
                           const float* __restrict__ w2,
                           const float* __restrict__ b2,
                           float* __restrict__ out,
                           int n) {
    __shared__ float sw1[32];
    __shared__ float sb1[16];
    __shared__ float sw2[256];
    __shared__ float sb2[16];

    int tid = threadIdx.x;
    if (tid < 32) sw1[tid] = w1[tid];
    if (tid < 16) sb1[tid] = b1[tid];
    if (tid >= 16 && tid < 32) sb2[tid - 16] = b2[tid - 16];
    for (int i = tid; i < 256; i += blockDim.x) sw2[i] = w2[i];
    __syncthreads();

    int i = blockIdx.x * blockDim.x + tid;
    if (i >= n) return;

    float xv = x[i];
    float lf = g_lf[i];

    float h[16];
#pragma unroll
    for (int j = 0; j < 16; j++) {
        float v = fmaf(xv, sw1[2 * j], fmaf(lf, sw1[2 * j + 1], sb1[j]));
        h[j] = fmaxf(v, 0.0f);
    }

    float o[16];
#pragma unroll
    for (int k = 0; k < 16; k++) {
        float s = sb2[k];
#pragma unroll
        for (int j = 0; j < 16; j++) {
            s = fmaf(h[j], sw2[k * 16 + j], s);
        }
        o[k] = fmaxf(s, 0.0f);
    }

    float4* o4 = reinterpret_cast<float4*>(out + (size_t)i * 16);
    o4[0] = make_float4(o[0], o[1], o[2], o[3]);
    o4[1] = make_float4(o[4], o[5], o[6], o[7]);
    o4[2] = make_float4(o[8], o[9], o[10], o[11]);
    o4[3] = make_float4(o[12], o[13], o[14], o[15]);
}

extern "C" void kernel_launch(void* const* d_in, const int* in_sizes, int n_in,
                              void* d_out, int out_size) {
    const float* x  = (const float*)d_in[0];
    const void*  ei = d_in[1];
    const float* w1 = (const float*)d_in[2];
    const float* b1 = (const float*)d_in[3];
    const float* w2 = (const float*)d_in[4];
    const float* b2 = (const float*)d_in[5];
    float*       out = (float*)d_out;

    int n = in_sizes[0];                        // x is [N, 1]
    long long E = (long long)in_sizes[1] / 2;   // edge_index is [2, E]

    const int TPB = 256;

    detect_kernel<<<1, 32>>>(ei, n, 128);
    zero_lf_kernel<<<(n + TPB - 1) / TPB, TPB>>>(n);

    long long nvec = E >> 2;
    long long nthreads = nvec + 1;  // +1 thread for the tail
    unsigned blocks = (unsigned)((nthreads + TPB - 1) / TPB);
    edge_kernel<<<blocks, TPB>>>(x, ei, E);

    mlp_kernel<<<(n + TPB - 1) / TPB, TPB>>>(x, w1, b1, w2, b2, out, n);
}

// round 5
// speedup vs baseline: 1.3624x; 1.3624x over previous
#include <cuda_runtime.h>
#include <cuda_fp16.h>

#define MAX_NODES (1 << 17)
__device__ float  g_lf[MAX_NODES];   // S[r] accumulator (pre-factored local field)
__device__ __half g_xh[MAX_NODES];   // fp16 copy of x for smem gather table
__device__ int    g_is32;            // 1 if edge_index is int32, 0 if int64

// Detect index width: interpret first `sample` values as int64; any value
// outside [0, n) means the data is really int32 (pairs fuse into huge ints).
__global__ void detect_kernel(const void* ei, int n, int sample) {
    if (threadIdx.x == 0 && blockIdx.x == 0) {
        const long long* p = (const long long*)ei;
        int is32 = 0;
        for (int i = 0; i < sample; i++) {
            long long v = p[i];
            if (v < 0 || v >= (long long)n) { is32 = 1; break; }
        }
        g_is32 = is32;
    }
}

// Zero the accumulator and build the fp16 gather table in one pass.
__global__ void prep_kernel(const float* __restrict__ x, int n) {
    int i = blockIdx.x * blockDim.x + threadIdx.x;
    if (i < n) {
        g_lf[i] = 0.0f;
        g_xh[i] = __float2half(x[i]);
    }
}

// Persistent edge kernel. Each CTA stages the full fp16 x table into dynamic
// smem, then streams edges: S[row] += (float)x_h[col].  x[row] gather is
// algebraically factored out (applied in the MLP kernel).
__global__ void __launch_bounds__(512, 1)
edge_kernel(const void* __restrict__ ei, long long E, int n) {
    extern __shared__ __half sx[];

    // Cooperative fill of the smem table (16B chunks).
    int nchunk = (n * 2 + 15) >> 4;   // int4 chunks (g_xh padded to MAX_NODES)
    const int4* src = reinterpret_cast<const int4*>(g_xh);
    int4* dst = reinterpret_cast<int4*>(sx);
    for (int i = threadIdx.x; i < nchunk; i += blockDim.x) dst[i] = src[i];
    __syncthreads();

    int is32 = g_is32;
    long long nvec = E >> 2;
    long long stride = (long long)gridDim.x * blockDim.x;

    for (long long t = (long long)blockIdx.x * blockDim.x + threadIdx.x;
         t < nvec; t += stride) {
        long long base = t << 2;
        int r[4], c[4];
        if (is32) {
            const int* rows = (const int*)ei;
            const int* cols = rows + E;
            int4 ra = *reinterpret_cast<const int4*>(rows + base);
            int4 ca = *reinterpret_cast<const int4*>(cols + base);
            r[0] = ra.x; r[1] = ra.y; r[2] = ra.z; r[3] = ra.w;
            c[0] = ca.x; c[1] = ca.y; c[2] = ca.z; c[3] = ca.w;
        } else {
            const long long* rows = (const long long*)ei;
            const long long* cols = rows + E;
            longlong2 ra = *reinterpret_cast<const longlong2*>(rows + base);
            longlong2 rb = *reinterpret_cast<const longlong2*>(rows + base + 2);
            longlong2 ca = *reinterpret_cast<const longlong2*>(cols + base);
            longlong2 cb = *reinterpret_cast<const longlong2*>(cols + base + 2);
            r[0] = (int)ra.x; r[1] = (int)ra.y; r[2] = (int)rb.x; r[3] = (int)rb.y;
            c[0] = (int)ca.x; c[1] = (int)ca.y; c[2] = (int)cb.x; c[3] = (int)cb.y;
        }
        float v[4];
#pragma unroll
        for (int k = 0; k < 4; k++) v[k] = __half2float(sx[c[k]]);
#pragma unroll
        for (int k = 0; k < 4; k++) atomicAdd(&g_lf[r[k]], v[k]);
    }

    // Tail (E not divisible by 4) — one thread.
    if (blockIdx.x == 0 && threadIdx.x == 0) {
        for (long long e = nvec << 2; e < E; e++) {
            int rr, cc;
            if (is32) {
                const int* rows = (const int*)ei;
                rr = rows[e]; cc = rows[E + e];
            } else {
                const long long* rows = (const long long*)ei;
                rr = (int)rows[e]; cc = (int)rows[E + e];
            }
            atomicAdd(&g_lf[rr], __half2float(sx[cc]));
        }
    }
}

// One thread per node. lf = x[i] * S[i] (factored multiply applied here).
__global__ void mlp_kernel(const float* __restrict__ x,
                           const float* __restrict__ w1,
                           const float* __restrict__ b1,
                           const float* __restrict__ w2,
                           const float* __restrict__ b2,
                           float* __restrict__ out,
                           int n) {
    __shared__ float sw1[32];
    __shared__ float sb1[16];
    __shared__ float sw2[256];
    __shared__ float sb2[16];

    int tid = threadIdx.x;
    if (tid < 32) sw1[tid] = w1[tid];
    if (tid < 16) sb1[tid] = b1[tid];
    if (tid >= 16 && tid < 32) sb2[tid - 16] = b2[tid - 16];
    for (int i = tid; i < 256; i += blockDim.x) sw2[i] = w2[i];
    __syncthreads();

    int i = blockIdx.x * blockDim.x + tid;
    if (i >= n) return;

    float xv = x[i];
    float lf = xv * g_lf[i];

    float h[16];
#pragma unroll
    for (int j = 0; j < 16; j++) {
        float v = fmaf(xv, sw1[2 * j], fmaf(lf, sw1[2 * j + 1], sb1[j]));
        h[j] = fmaxf(v, 0.0f);
    }

    float o[16];
#pragma unroll
    for (int k = 0; k < 16; k++) {
        float s = sb2[k];
#pragma unroll
        for (int j = 0; j < 16; j++) {
            s = fmaf(h[j], sw2[k * 16 + j], s);
        }
        o[k] = fmaxf(s, 0.0f);
    }

    float4* o4 = reinterpret_cast<float4*>(out + (size_t)i * 16);
    o4[0] = make_float4(o[0], o[1], o[2], o[3]);
    o4[1] = make_float4(o[4], o[5], o[6], o[7]);
    o4[2] = make_float4(o[8], o[9], o[10], o[11]);
    o4[3] = make_float4(o[12], o[13], o[14], o[15]);
}

extern "C" void kernel_launch(void* const* d_in, const int* in_sizes, int n_in,
                              void* d_out, int out_size) {
    const float* x  = (const float*)d_in[0];
    const void*  ei = d_in[1];
    const float* w1 = (const float*)d_in[2];
    const float* b1 = (const float*)d_in[3];
    const float* w2 = (const float*)d_in[4];
    const float* b2 = (const float*)d_in[5];
    float*       out = (float*)d_out;

    int n = in_sizes[0];                        // x is [N, 1]
    long long E = (long long)in_sizes[1] / 2;   // edge_index is [2, E]

    const int TPB = 256;
    size_t smem_bytes = ((size_t)n * 2 + 15) & ~(size_t)15;

    // Host-side attribute set; executes immediately (not a stream op), legal
    // under graph capture, idempotent across calls.
    cudaFuncSetAttribute(edge_kernel,
                         cudaFuncAttributeMaxDynamicSharedMemorySize,
                         (int)smem_bytes);

    detect_kernel<<<1, 32>>>(ei, n, 128);
    prep_kernel<<<(n + TPB - 1) / TPB, TPB>>>(x, n);

    edge_kernel<<<148, 512, smem_bytes>>>(ei, E, n);

    mlp_kernel<<<(n + TPB - 1) / TPB, TPB>>>(x, w1, b1, w2, b2, out, n);
}